// round 9
// baseline (speedup 1.0000x reference)
#include <cuda_runtime.h>
#include <cuda_bf16.h>
#include <math.h>
#include <cstdint>

#define BATCH 4
#define SEQ   2048
#define DM    1024
#define NH    16
#define HD    64
#define QKVN  (3*DM)
#define MROWS (BATCH*SEQ)   // 8192

// ---------------------------------------------------------------------------
// Persistent bf16 hi/lo arrays (no dynamic allocation allowed)
// ---------------------------------------------------------------------------
__device__ __nv_bfloat16 g_xh[(size_t)MROWS * DM];
__device__ __nv_bfloat16 g_xl[(size_t)MROWS * DM];
__device__ __nv_bfloat16 g_wqh[(size_t)DM * QKVN];
__device__ __nv_bfloat16 g_wql[(size_t)DM * QKVN];
__device__ __nv_bfloat16 g_woh[(size_t)DM * DM];
__device__ __nv_bfloat16 g_wol[(size_t)DM * DM];
__device__ __nv_bfloat16 g_qkvh[(size_t)MROWS * QKVN];
__device__ __nv_bfloat16 g_qkvl[(size_t)MROWS * QKVN];
__device__ __nv_bfloat16 g_atth[(size_t)MROWS * DM];
__device__ __nv_bfloat16 g_attl[(size_t)MROWS * DM];

// ===========================================================================
// Helpers
// ===========================================================================
__device__ __forceinline__ void ldsm_x4(uint32_t* r, uint32_t addr) {
    asm volatile("ldmatrix.sync.aligned.m8n8.x4.shared.b16 {%0,%1,%2,%3}, [%4];"
        : "=r"(r[0]), "=r"(r[1]), "=r"(r[2]), "=r"(r[3]) : "r"(addr));
}
__device__ __forceinline__ void ldsm_x4_t(uint32_t* r, uint32_t addr) {
    asm volatile("ldmatrix.sync.aligned.m8n8.x4.trans.shared.b16 {%0,%1,%2,%3}, [%4];"
        : "=r"(r[0]), "=r"(r[1]), "=r"(r[2]), "=r"(r[3]) : "r"(addr));
}
__device__ __forceinline__ void mma16816(float* d, const uint32_t* a, const uint32_t* b) {
    asm volatile(
        "mma.sync.aligned.m16n8k16.row.col.f32.bf16.bf16.f32 "
        "{%0,%1,%2,%3}, {%4,%5,%6,%7}, {%8,%9}, {%0,%1,%2,%3};"
        : "+f"(d[0]), "+f"(d[1]), "+f"(d[2]), "+f"(d[3])
        : "r"(a[0]), "r"(a[1]), "r"(a[2]), "r"(a[3]), "r"(b[0]), "r"(b[1]));
}
__device__ __forceinline__ uint32_t smem_to_u32(const void* smem_ptr) {
    uint32_t addr;
    asm("{ .reg .u64 tmp; cvta.to.shared.u64 tmp, %1; cvt.u32.u64 %0, tmp; }"
        : "=r"(addr) : "l"(smem_ptr));
    return addr;
}
__device__ __forceinline__ float ex2f(float x) {
    float y;
    asm("ex2.approx.f32 %0, %1;" : "=f"(y) : "f"(x));
    return y;
}
__device__ __forceinline__ uint32_t pack_bf16_pair(float x0, float x1) {
    __nv_bfloat162 t = __floats2bfloat162_rn(x0, x1);
    return *(uint32_t*)&t;
}
__device__ __forceinline__ void split_f32(float x, float& h, float& l) {
    __nv_bfloat16 hb = __float2bfloat16_rn(x);
    h = __bfloat162float(hb);
    l = x - h;
}

#define CP_ASYNC16(saddr, gptr) \
    asm volatile("cp.async.cg.shared.global [%0], [%1], 16;" \
                 :: "r"(saddr), "l"(gptr))
#define CP_COMMIT()  asm volatile("cp.async.commit_group;")
#define CP_WAIT0()   asm volatile("cp.async.wait_group 0;")
#define CP_WAIT1()   asm volatile("cp.async.wait_group 1;")

// ===========================================================================
// Split kernel: fp32 -> bf16 hi/lo
// ===========================================================================
__global__ void split_kernel(const float* __restrict__ s,
                             __nv_bfloat16* __restrict__ h,
                             __nv_bfloat16* __restrict__ l, int n4)
{
    int i = blockIdx.x * blockDim.x + threadIdx.x;
    if (i >= n4) return;
    float4 v = ((const float4*)s)[i];
    float h0,l0,h1,l1,h2,l2,h3,l3;
    split_f32(v.x, h0, l0); split_f32(v.y, h1, l1);
    split_f32(v.z, h2, l2); split_f32(v.w, h3, l3);
    ((uint2*)h)[i] = make_uint2(pack_bf16_pair(h0, h1), pack_bf16_pair(h2, h3));
    ((uint2*)l)[i] = make_uint2(pack_bf16_pair(l0, l1), pack_bf16_pair(l2, l3));
}

// ===========================================================================
// cp.async bf16x3 GEMM: C = A @ B; A,B pre-split hi/lo bf16 in global.
// CTA tile 128x256, BK=32, 512 threads (16 warps, 32x64 warp tiles, 4x4).
// 3-stage cp.async ring. MMA pass-reordered over nb-pairs: same-accumulator
// dependency distance 8 for tensor-pipe latency hiding.
// ===========================================================================
#define GOAH 0
#define GOAL 10240
#define GOBH 20480
#define GOBL 37376
#define GSTAGE_B 54272
#define GEMM_SMEM_BYTES (3 * GSTAGE_B)   // 162816

__global__ __launch_bounds__(512, 1)
void gemm_async(const __nv_bfloat16* __restrict__ Ah, const __nv_bfloat16* __restrict__ Al,
                const __nv_bfloat16* __restrict__ Bh, const __nv_bfloat16* __restrict__ Bl,
                float* __restrict__ Cf,
                __nv_bfloat16* __restrict__ Ch, __nv_bfloat16* __restrict__ Cl,
                int M, int N, int K, float qscale, int qcols)
{
    extern __shared__ char smem[];
    const uint32_t su = smem_to_u32(smem);

    const int tid = threadIdx.x;
    const int wid = tid >> 5;
    const int lid = tid & 31;
    const int brow = blockIdx.y * 128;
    const int bcol = blockIdx.x * 256;

    const int wr = wid >> 2;     // 0..3 -> m offset wr*32
    const int wc = wid & 3;      // 0..3 -> n offset wc*64

    const int nkt = K >> 5;

    // copy-thread assignments (512 threads)
    const int ar  = tid >> 2;            // A row 0..127
    const int ac  = tid & 3;             // A 16B chunk 0..3
    const int br  = tid >> 4;            // B row 0..31
    const int bc  = (tid & 15) * 2;      // B chunk base (2 chunks of 16B)

    auto issue_tile = [&](int kt) {
        const uint32_t sb = su + (uint32_t)(kt % 3) * GSTAGE_B;
        const int k0 = kt << 5;
        const __nv_bfloat16* gah = Ah + (size_t)(brow + ar) * K + k0 + ac * 8;
        const __nv_bfloat16* gal = Al + (size_t)(brow + ar) * K + k0 + ac * 8;
        CP_ASYNC16(sb + GOAH + ar * 80 + ac * 16, gah);
        CP_ASYNC16(sb + GOAL + ar * 80 + ac * 16, gal);
        const __nv_bfloat16* gbh = Bh + (size_t)(k0 + br) * N + bcol + bc * 8;
        const __nv_bfloat16* gbl = Bl + (size_t)(k0 + br) * N + bcol + bc * 8;
        uint32_t sbh = sb + GOBH + br * 528 + bc * 16;
        uint32_t sbl = sb + GOBL + br * 528 + bc * 16;
        CP_ASYNC16(sbh,      gbh);
        CP_ASYNC16(sbh + 16, gbh + 8);
        CP_ASYNC16(sbl,      gbl);
        CP_ASYNC16(sbl + 16, gbl + 8);
    };

    float acc[2][8][4];
#pragma unroll
    for (int i = 0; i < 2; i++)
#pragma unroll
        for (int j = 0; j < 8; j++)
#pragma unroll
            for (int q = 0; q < 4; q++) acc[i][j][q] = 0.f;

    issue_tile(0); CP_COMMIT();
    issue_tile(1); CP_COMMIT();

    for (int kt = 0; kt < nkt; kt++) {
        if (kt + 1 < nkt) { CP_WAIT1(); } else { CP_WAIT0(); }
        __syncthreads();
        if (kt + 2 < nkt) { issue_tile(kt + 2); CP_COMMIT(); }

        const uint32_t sb = su + (uint32_t)(kt % 3) * GSTAGE_B;
#pragma unroll
        for (int ks = 0; ks < 2; ks++) {
            uint32_t ah[2][4], al[2][4];
#pragma unroll
            for (int mi = 0; mi < 2; mi++) {
                uint32_t row = wr * 32 + mi * 16 + (lid & 15);
                uint32_t col = ks * 16 + (lid >> 4) * 8;
                uint32_t off = row * 80 + col * 2;
                ldsm_x4(ah[mi], sb + GOAH + off);
                ldsm_x4(al[mi], sb + GOAL + off);
            }
            // process nb tiles in pairs; pass-major over each pair:
            // same-accumulator dependency distance = 8 MMAs
#pragma unroll
            for (int nbp = 0; nbp < 2; nbp++) {
                uint32_t bh[2][4], bl[2][4];
#pragma unroll
                for (int i = 0; i < 2; i++) {
                    const int nb = nbp * 2 + i;
                    uint32_t row = ks * 16 + (lid & 15);
                    uint32_t col = wc * 64 + nb * 16 + (lid >> 4) * 8;
                    uint32_t off = row * 528 + col * 2;
                    ldsm_x4_t(bh[i], sb + GOBH + off);
                    ldsm_x4_t(bl[i], sb + GOBL + off);
                }
#pragma unroll
                for (int pass = 0; pass < 3; pass++) {
#pragma unroll
                    for (int i = 0; i < 2; i++) {
                        const int nb = nbp * 2 + i;
#pragma unroll
                        for (int mi = 0; mi < 2; mi++) {
                            const uint32_t* af = (pass == 2) ? al[mi] : ah[mi];
                            const uint32_t* bf = (pass == 1) ? bl[i] : bh[i];
                            mma16816(acc[mi][nb * 2],     af, &bf[0]);
                            mma16816(acc[mi][nb * 2 + 1], af, &bf[2]);
                        }
                    }
                }
            }
        }
    }

    // ---- epilogue ----
    const int qrow = lid >> 2;
    const int qcol = (lid & 3) * 2;
#pragma unroll
    for (int mi = 0; mi < 2; mi++) {
        int r0 = brow + wr * 32 + mi * 16 + qrow;
#pragma unroll
        for (int nb8 = 0; nb8 < 8; nb8++) {
            int c0 = bcol + wc * 64 + nb8 * 8 + qcol;
            float* d = acc[mi][nb8];
            if (Cf) {
                *(float2*)(Cf + (size_t)r0 * N + c0)       = make_float2(d[0], d[1]);
                *(float2*)(Cf + (size_t)(r0 + 8) * N + c0) = make_float2(d[2], d[3]);
            } else {
                const float sc = (c0 < qcols) ? qscale : 1.f;
                float h0,l0,h1,l1;
                split_f32(d[0] * sc, h0, l0); split_f32(d[1] * sc, h1, l1);
                *(uint32_t*)(Ch + (size_t)r0 * N + c0) = pack_bf16_pair(h0, h1);
                *(uint32_t*)(Cl + (size_t)r0 * N + c0) = pack_bf16_pair(l0, l1);
                split_f32(d[2] * sc, h0, l0); split_f32(d[3] * sc, h1, l1);
                *(uint32_t*)(Ch + (size_t)(r0 + 8) * N + c0) = pack_bf16_pair(h0, h1);
                *(uint32_t*)(Cl + (size_t)(r0 + 8) * N + c0) = pack_bf16_pair(l0, l1);
            }
        }
    }
}

// ===========================================================================
// HMMA flash attention, bf16x3, cp.async-fed K/V (pre-split in g_qkvh/l).
// Grid: (SEQ/256, NH, BATCH). 512 threads = 16 warps; warp w owns q rows
// [w*16, w*16+16). Q persists in smem; K/V 3-stage ring, 1 barrier/block.
// S and PV loops pass-reordered over j2-pairs: same-acc distance 8 (was 1).
// ===========================================================================
#define SK 72
#define AQHI 0
#define AQLO (256 * SK * 2)            // 36864
#define AKV  (2 * 256 * SK * 2)        // 73728
#define KVST (4 * 64 * SK * 2)         // 36864 per stage
#define OKHI 0
#define OKLO (64 * SK * 2)             // 9216
#define OVHI (2 * 64 * SK * 2)
#define OVLO (3 * 64 * SK * 2)
#define ATTN_SMEM_BYTES (AKV + 3 * KVST)   // 184320

__global__ __launch_bounds__(512, 1)
void attn_hmma()
{
    extern __shared__ char dsm[];
    const uint32_t su = smem_to_u32(dsm);

    const int tid = threadIdx.x;
    const int wid = tid >> 5;
    const int lid = tid & 31;
    const int b  = blockIdx.z;
    const int h  = blockIdx.y;
    const int q0 = blockIdx.x * 256;

    const uint32_t uQhi = su + AQHI, uQlo = su + AQLO;

    // KV copy assignment (512 thr)
    const int cv_arr = tid >> 7;
    const int cv_r   = (tid >> 1) & 63;
    const int cv_c   = (tid & 1) * 4;
    const __nv_bfloat16* cv_base = (cv_arr & 1) ? g_qkvl : g_qkvh;
    const int cv_col = DM + (cv_arr >> 1) * DM + h * HD + cv_c * 8;

    auto issue_kv = [&](int kb) {
        const uint32_t sb = su + AKV + (uint32_t)(kb % 3) * KVST
                            + cv_arr * (64 * SK * 2) + cv_r * (SK * 2) + cv_c * 16;
        const __nv_bfloat16* gp = cv_base +
            (size_t)(b * SEQ + kb * 64 + cv_r) * QKVN + cv_col;
#pragma unroll
        for (int c = 0; c < 4; c++)
            CP_ASYNC16(sb + c * 16, gp + c * 8);
    };

    // ---- issue Q + KV block 0 as group 0
    {
        const int qr = tid >> 1;
        const __nv_bfloat16* gq =
            ((tid & 1) ? g_qkvl : g_qkvh) + (size_t)(b * SEQ + q0 + qr) * QKVN + h * HD;
        uint32_t sq = ((tid & 1) ? uQlo : uQhi) + qr * (SK * 2);
#pragma unroll
        for (int c = 0; c < 8; c++)
            CP_ASYNC16(sq + c * 16, gq + c * 8);
    }
    issue_kv(0); CP_COMMIT();
    issue_kv(1); CP_COMMIT();

    float o[8][4];
#pragma unroll
    for (int j = 0; j < 8; j++)
#pragma unroll
        for (int q = 0; q < 4; q++) o[j][q] = 0.f;
    float m0 = -1e30f, m1 = -1e30f, l0 = 0.f, l1 = 0.f;

    for (int kb = 0; kb < SEQ / 64; kb++) {
        if (kb + 1 < SEQ / 64) { CP_WAIT1(); } else { CP_WAIT0(); }
        __syncthreads();
        if (kb + 2 < SEQ / 64) { issue_kv(kb + 2); CP_COMMIT(); }

        const uint32_t stB = su + AKV + (uint32_t)(kb % 3) * KVST;
        const uint32_t uKhi = stB + OKHI, uKlo = stB + OKLO;
        const uint32_t uVhi = stB + OVHI, uVlo = stB + OVLO;

        // ---- S = Q K^T  (16 x 64 per warp), bf16x3, pass-major over j2 pairs
        float s[8][4];
#pragma unroll
        for (int j = 0; j < 8; j++)
#pragma unroll
            for (int q = 0; q < 4; q++) s[j][q] = 0.f;

#pragma unroll
        for (int t = 0; t < 4; t++) {
            uint32_t qh[4], ql[4];
            {
                uint32_t row = wid * 16 + (lid & 15);
                uint32_t off = (row * SK + t * 16 + (lid >> 4) * 8) * 2;
                ldsm_x4(qh, uQhi + off);
                ldsm_x4(ql, uQlo + off);
            }
#pragma unroll
            for (int jp = 0; jp < 2; jp++) {
                uint32_t kh[2][4], kl[2][4];
#pragma unroll
                for (int i = 0; i < 2; i++) {
                    const int j2 = jp * 2 + i;
                    uint32_t off = ((j2 * 16 + (lid & 7) + ((lid >> 4) & 1) * 8) * SK
                                    + t * 16 + ((lid >> 3) & 1) * 8) * 2;
                    ldsm_x4(kh[i], uKhi + off);
                    ldsm_x4(kl[i], uKlo + off);
                }
#pragma unroll
                for (int pass = 0; pass < 3; pass++) {
#pragma unroll
                    for (int i = 0; i < 2; i++) {
                        const int j2 = jp * 2 + i;
                        const uint32_t* af = (pass == 2) ? ql : qh;
                        const uint32_t* bf = (pass == 1) ? kl[i] : kh[i];
                        mma16816(s[j2 * 2],     af, &bf[0]);
                        mma16816(s[j2 * 2 + 1], af, &bf[2]);
                    }
                }
            }
        }

        // ---- online softmax (log2 domain) + pack P
        uint32_t phi[4][4], plo[4][4];
        {
            float mx0 = s[0][0], mx1 = s[0][2];
#pragma unroll
            for (int j = 0; j < 8; j++) {
                mx0 = fmaxf(mx0, fmaxf(s[j][0], s[j][1]));
                mx1 = fmaxf(mx1, fmaxf(s[j][2], s[j][3]));
            }
            mx0 = fmaxf(mx0, __shfl_xor_sync(0xffffffff, mx0, 1));
            mx0 = fmaxf(mx0, __shfl_xor_sync(0xffffffff, mx0, 2));
            mx1 = fmaxf(mx1, __shfl_xor_sync(0xffffffff, mx1, 1));
            mx1 = fmaxf(mx1, __shfl_xor_sync(0xffffffff, mx1, 2));

            const float mn0 = fmaxf(m0, mx0);
            const float mn1 = fmaxf(m1, mx1);
            const float c0 = ex2f(m0 - mn0);
            const float c1 = ex2f(m1 - mn1);
            m0 = mn0; m1 = mn1;

            float rl0 = 0.f, rl1 = 0.f;
#pragma unroll
            for (int j = 0; j < 8; j++) {
                s[j][0] = ex2f(s[j][0] - mn0); rl0 += s[j][0];
                s[j][1] = ex2f(s[j][1] - mn0); rl0 += s[j][1];
                s[j][2] = ex2f(s[j][2] - mn1); rl1 += s[j][2];
                s[j][3] = ex2f(s[j][3] - mn1); rl1 += s[j][3];
            }
            rl0 += __shfl_xor_sync(0xffffffff, rl0, 1);
            rl0 += __shfl_xor_sync(0xffffffff, rl0, 2);
            rl1 += __shfl_xor_sync(0xffffffff, rl1, 1);
            rl1 += __shfl_xor_sync(0xffffffff, rl1, 2);
            l0 = l0 * c0 + rl0;
            l1 = l1 * c1 + rl1;

#pragma unroll
            for (int j = 0; j < 8; j++) {
                o[j][0] *= c0; o[j][1] *= c0;
                o[j][2] *= c1; o[j][3] *= c1;
            }

#pragma unroll
            for (int t = 0; t < 4; t++) {
                const int j = 2 * t;
                float h0,lo0,h1,lo1;
                split_f32(s[j][0], h0, lo0);   split_f32(s[j][1], h1, lo1);
                phi[t][0] = pack_bf16_pair(h0, h1);  plo[t][0] = pack_bf16_pair(lo0, lo1);
                split_f32(s[j][2], h0, lo0);   split_f32(s[j][3], h1, lo1);
                phi[t][1] = pack_bf16_pair(h0, h1);  plo[t][1] = pack_bf16_pair(lo0, lo1);
                split_f32(s[j+1][0], h0, lo0); split_f32(s[j+1][1], h1, lo1);
                phi[t][2] = pack_bf16_pair(h0, h1);  plo[t][2] = pack_bf16_pair(lo0, lo1);
                split_f32(s[j+1][2], h0, lo0); split_f32(s[j+1][3], h1, lo1);
                phi[t][3] = pack_bf16_pair(h0, h1);  plo[t][3] = pack_bf16_pair(lo0, lo1);
            }
        }

        // ---- O += P V  (bf16x3), pass-major over j2 pairs
#pragma unroll
        for (int t = 0; t < 4; t++) {
#pragma unroll
            for (int jp = 0; jp < 2; jp++) {
                uint32_t vh[2][4], vl[2][4];
#pragma unroll
                for (int i = 0; i < 2; i++) {
                    const int j2 = jp * 2 + i;
                    uint32_t off = ((t * 16 + (lid & 15)) * SK
                                    + j2 * 16 + (lid >> 4) * 8) * 2;
                    ldsm_x4_t(vh[i], uVhi + off);
                    ldsm_x4_t(vl[i], uVlo + off);
                }
#pragma unroll
                for (int pass = 0; pass < 3; pass++) {
#pragma unroll
                    for (int i = 0; i < 2; i++) {
                        const int j2 = jp * 2 + i;
                        const uint32_t* af = (pass == 2) ? plo[t] : phi[t];
                        const uint32_t* bf = (pass == 1) ? vl[i] : vh[i];
                        mma16816(o[j2 * 2],     af, &bf[0]);
                        mma16816(o[j2 * 2 + 1], af, &bf[2]);
                    }
                }
            }
        }
    }

    // ---- epilogue: write hi/lo bf16 attention output
    {
        const float inv0 = 1.f / l0;
        const float inv1 = 1.f / l1;
        const int gr0 = q0 + wid * 16 + (lid >> 2);
        const int col = h * HD + (lid & 3) * 2;
#pragma unroll
        for (int j = 0; j < 8; j++) {
            size_t i0 = (size_t)(b * SEQ + gr0) * DM + col + j * 8;
            size_t i1 = (size_t)(b * SEQ + gr0 + 8) * DM + col + j * 8;
            float h0,lo0,h1,lo1;
            split_f32(o[j][0] * inv0, h0, lo0);
            split_f32(o[j][1] * inv0, h1, lo1);
            *(uint32_t*)(g_atth + i0) = pack_bf16_pair(h0, h1);
            *(uint32_t*)(g_attl + i0) = pack_bf16_pair(lo0, lo1);
            split_f32(o[j][2] * inv1, h0, lo0);
            split_f32(o[j][3] * inv1, h1, lo1);
            *(uint32_t*)(g_atth + i1) = pack_bf16_pair(h0, h1);
            *(uint32_t*)(g_attl + i1) = pack_bf16_pair(lo0, lo1);
        }
    }
}

// ---------------------------------------------------------------------------
extern "C" void kernel_launch(void* const* d_in, const int* in_sizes, int n_in,
                              void* d_out, int out_size)
{
    const float* x     = (const float*)d_in[0];   // [4,2048,1024]
    const float* w_qkv = (const float*)d_in[1];   // [1024,3072]
    const float* w_out = (const float*)d_in[2];   // [1024,1024]
    float* out = (float*)d_out;                   // [4,2048,1024]

    __nv_bfloat16 *xh, *xl, *wqh, *wql, *woh, *wol, *qkvh, *qkvl, *atth, *attl;
    cudaGetSymbolAddress((void**)&xh,  g_xh);   cudaGetSymbolAddress((void**)&xl,  g_xl);
    cudaGetSymbolAddress((void**)&wqh, g_wqh);  cudaGetSymbolAddress((void**)&wql, g_wql);
    cudaGetSymbolAddress((void**)&woh, g_woh);  cudaGetSymbolAddress((void**)&wol, g_wol);
    cudaGetSymbolAddress((void**)&qkvh, g_qkvh); cudaGetSymbolAddress((void**)&qkvl, g_qkvl);
    cudaGetSymbolAddress((void**)&atth, g_atth); cudaGetSymbolAddress((void**)&attl, g_attl);

    cudaFuncSetAttribute(gemm_async,
                         cudaFuncAttributeMaxDynamicSharedMemorySize,
                         GEMM_SMEM_BYTES);
    cudaFuncSetAttribute(attn_hmma,
                         cudaFuncAttributeMaxDynamicSharedMemorySize,
                         ATTN_SMEM_BYTES);

    const float QSCALE = 0.125f * 1.4426950408889634f;   // (1/sqrt(64))*log2(e)

    // 0) split inputs to bf16 hi/lo
    {
        int n4x = MROWS * DM / 4;
        split_kernel<<<(n4x + 255) / 256, 256>>>(x, xh, xl, n4x);
        int n4q = DM * QKVN / 4;
        split_kernel<<<(n4q + 255) / 256, 256>>>(w_qkv, wqh, wql, n4q);
        int n4o = DM * DM / 4;
        split_kernel<<<(n4o + 255) / 256, 256>>>(w_out, woh, wol, n4o);
    }

    // 1) QKV projection -> hi/lo bf16 (Q columns pre-scaled by QSCALE)
    {
        dim3 grid(QKVN / 256, MROWS / 128);
        gemm_async<<<grid, 512, GEMM_SMEM_BYTES>>>(
            xh, xl, wqh, wql, nullptr, qkvh, qkvl,
            MROWS, QKVN, DM, QSCALE, DM);
    }

    // 2) Attention (HMMA flash, cp.async K/V)
    {
        dim3 grid(SEQ / 256, NH, BATCH);
        attn_hmma<<<grid, 512, ATTN_SMEM_BYTES>>>();
    }

    // 3) Output projection -> fp32 d_out
    {
        dim3 grid(DM / 256, MROWS / 128);
        gemm_async<<<grid, 512, GEMM_SMEM_BYTES>>>(
            atth, attl, woh, wol, out, nullptr, nullptr,
            MROWS, DM, DM, 1.f, 0);
    }
}

// round 10
// speedup vs baseline: 1.4295x; 1.4295x over previous
#include <cuda_runtime.h>
#include <cuda_fp16.h>
#include <math.h>
#include <cstdint>

#define BATCH 4
#define SEQ   2048
#define DM    1024
#define NH    16
#define HD    64
#define QKVN  (3*DM)
#define MROWS (BATCH*SEQ)   // 8192

// ---------------------------------------------------------------------------
// Persistent fp16 hi/lo arrays (no dynamic allocation allowed)
// ---------------------------------------------------------------------------
__device__ __half g_xh[(size_t)MROWS * DM];
__device__ __half g_xl[(size_t)MROWS * DM];
__device__ __half g_wqh[(size_t)DM * QKVN];
__device__ __half g_wql[(size_t)DM * QKVN];     // written, unused (B needs hi only)
__device__ __half g_woh[(size_t)DM * DM];
__device__ __half g_wol[(size_t)DM * DM];       // written, unused
__device__ __half g_qkvh[(size_t)MROWS * QKVN];
__device__ __half g_qkvl[(size_t)MROWS * QKVN];
__device__ __half g_atth[(size_t)MROWS * DM];
__device__ __half g_attl[(size_t)MROWS * DM];

// ===========================================================================
// Helpers
// ===========================================================================
__device__ __forceinline__ void ldsm_x4(uint32_t* r, uint32_t addr) {
    asm volatile("ldmatrix.sync.aligned.m8n8.x4.shared.b16 {%0,%1,%2,%3}, [%4];"
        : "=r"(r[0]), "=r"(r[1]), "=r"(r[2]), "=r"(r[3]) : "r"(addr));
}
__device__ __forceinline__ void ldsm_x4_t(uint32_t* r, uint32_t addr) {
    asm volatile("ldmatrix.sync.aligned.m8n8.x4.trans.shared.b16 {%0,%1,%2,%3}, [%4];"
        : "=r"(r[0]), "=r"(r[1]), "=r"(r[2]), "=r"(r[3]) : "r"(addr));
}
__device__ __forceinline__ void mma16816(float* d, const uint32_t* a, const uint32_t* b) {
    asm volatile(
        "mma.sync.aligned.m16n8k16.row.col.f32.f16.f16.f32 "
        "{%0,%1,%2,%3}, {%4,%5,%6,%7}, {%8,%9}, {%0,%1,%2,%3};"
        : "+f"(d[0]), "+f"(d[1]), "+f"(d[2]), "+f"(d[3])
        : "r"(a[0]), "r"(a[1]), "r"(a[2]), "r"(a[3]), "r"(b[0]), "r"(b[1]));
}
__device__ __forceinline__ uint32_t smem_to_u32(const void* smem_ptr) {
    uint32_t addr;
    asm("{ .reg .u64 tmp; cvta.to.shared.u64 tmp, %1; cvt.u32.u64 %0, tmp; }"
        : "=r"(addr) : "l"(smem_ptr));
    return addr;
}
__device__ __forceinline__ float ex2f(float x) {
    float y;
    asm("ex2.approx.f32 %0, %1;" : "=f"(y) : "f"(x));
    return y;
}
__device__ __forceinline__ uint32_t pack_h2(float x0, float x1) {
    __half2 t = __floats2half2_rn(x0, x1);
    return *(uint32_t*)&t;
}
__device__ __forceinline__ void split_h(float x, float& h, float& l) {
    __half hh = __float2half_rn(x);
    h = __half2float(hh);
    l = x - h;
}

#define CP_ASYNC16(saddr, gptr) \
    asm volatile("cp.async.cg.shared.global [%0], [%1], 16;" \
                 :: "r"(saddr), "l"(gptr))
#define CP_COMMIT()  asm volatile("cp.async.commit_group;")
#define CP_WAIT0()   asm volatile("cp.async.wait_group 0;")
#define CP_WAIT1()   asm volatile("cp.async.wait_group 1;")

// ===========================================================================
// Split kernel: fp32 -> fp16 hi/lo
// ===========================================================================
__global__ void split_kernel(const float* __restrict__ s,
                             __half* __restrict__ h,
                             __half* __restrict__ l, int n4)
{
    int i = blockIdx.x * blockDim.x + threadIdx.x;
    if (i >= n4) return;
    float4 v = ((const float4*)s)[i];
    float h0,l0,h1,l1,h2,l2,h3,l3;
    split_h(v.x, h0, l0); split_h(v.y, h1, l1);
    split_h(v.z, h2, l2); split_h(v.w, h3, l3);
    ((uint2*)h)[i] = make_uint2(pack_h2(h0, h1), pack_h2(h2, h3));
    ((uint2*)l)[i] = make_uint2(pack_h2(l0, l1), pack_h2(l2, l3));
}

// ===========================================================================
// cp.async fp16x2 GEMM: C = (Ah+Al) @ Bh; operands pre-split fp16 in global.
// CTA tile 128x256, BK=32, 512 threads (16 warps, 32x64 warp tiles, 4x4).
// 3-stage cp.async ring; 2 MMAs per logical product.
// ===========================================================================
#define GOAH 0
#define GOAL 10240
#define GOBH 20480
#define GSTAGE_B 37376           // 20480 + 32*528
#define GEMM_SMEM_BYTES (3 * GSTAGE_B)   // 112128

__global__ __launch_bounds__(512, 1)
void gemm_async(const __half* __restrict__ Ah, const __half* __restrict__ Al,
                const __half* __restrict__ Bh,
                float* __restrict__ Cf,
                __half* __restrict__ Ch, __half* __restrict__ Cl,
                int M, int N, int K, float qscale, int qcols)
{
    extern __shared__ char smem[];
    const uint32_t su = smem_to_u32(smem);

    const int tid = threadIdx.x;
    const int wid = tid >> 5;
    const int lid = tid & 31;
    const int brow = blockIdx.y * 128;
    const int bcol = blockIdx.x * 256;

    const int wr = wid >> 2;     // 0..3 -> m offset wr*32
    const int wc = wid & 3;      // 0..3 -> n offset wc*64

    const int nkt = K >> 5;

    // copy-thread assignments (512 threads)
    const int ar  = tid >> 2;            // A row 0..127
    const int ac  = tid & 3;             // A 16B chunk 0..3
    const int br  = tid >> 4;            // B row 0..31
    const int bc  = (tid & 15) * 2;      // B chunk base (2 chunks of 16B)

    auto issue_tile = [&](int kt) {
        const uint32_t sb = su + (uint32_t)(kt % 3) * GSTAGE_B;
        const int k0 = kt << 5;
        const __half* gah = Ah + (size_t)(brow + ar) * K + k0 + ac * 8;
        const __half* gal = Al + (size_t)(brow + ar) * K + k0 + ac * 8;
        CP_ASYNC16(sb + GOAH + ar * 80 + ac * 16, gah);
        CP_ASYNC16(sb + GOAL + ar * 80 + ac * 16, gal);
        const __half* gbh = Bh + (size_t)(k0 + br) * N + bcol + bc * 8;
        uint32_t sbh = sb + GOBH + br * 528 + bc * 16;
        CP_ASYNC16(sbh,      gbh);
        CP_ASYNC16(sbh + 16, gbh + 8);
    };

    float acc[2][8][4];
#pragma unroll
    for (int i = 0; i < 2; i++)
#pragma unroll
        for (int j = 0; j < 8; j++)
#pragma unroll
            for (int q = 0; q < 4; q++) acc[i][j][q] = 0.f;

    issue_tile(0); CP_COMMIT();
    issue_tile(1); CP_COMMIT();

    for (int kt = 0; kt < nkt; kt++) {
        if (kt + 1 < nkt) { CP_WAIT1(); } else { CP_WAIT0(); }
        __syncthreads();
        if (kt + 2 < nkt) { issue_tile(kt + 2); CP_COMMIT(); }

        const uint32_t sb = su + (uint32_t)(kt % 3) * GSTAGE_B;
#pragma unroll
        for (int ks = 0; ks < 2; ks++) {
            uint32_t ah[2][4], al[2][4];
#pragma unroll
            for (int mi = 0; mi < 2; mi++) {
                uint32_t row = wr * 32 + mi * 16 + (lid & 15);
                uint32_t col = ks * 16 + (lid >> 4) * 8;
                uint32_t off = row * 80 + col * 2;
                ldsm_x4(ah[mi], sb + GOAH + off);
                ldsm_x4(al[mi], sb + GOAL + off);
            }
#pragma unroll
            for (int nbp = 0; nbp < 2; nbp++) {
                uint32_t bh[2][4];
#pragma unroll
                for (int i = 0; i < 2; i++) {
                    const int nb = nbp * 2 + i;
                    uint32_t row = ks * 16 + (lid & 15);
                    uint32_t col = wc * 64 + nb * 16 + (lid >> 4) * 8;
                    ldsm_x4_t(bh[i], sb + GOBH + row * 528 + col * 2);
                }
#pragma unroll
                for (int pass = 0; pass < 2; pass++) {
#pragma unroll
                    for (int i = 0; i < 2; i++) {
                        const int nb = nbp * 2 + i;
#pragma unroll
                        for (int mi = 0; mi < 2; mi++) {
                            const uint32_t* af = pass ? al[mi] : ah[mi];
                            mma16816(acc[mi][nb * 2],     af, &bh[i][0]);
                            mma16816(acc[mi][nb * 2 + 1], af, &bh[i][2]);
                        }
                    }
                }
            }
        }
    }

    // ---- epilogue ----
    const int qrow = lid >> 2;
    const int qcol = (lid & 3) * 2;
#pragma unroll
    for (int mi = 0; mi < 2; mi++) {
        int r0 = brow + wr * 32 + mi * 16 + qrow;
#pragma unroll
        for (int nb8 = 0; nb8 < 8; nb8++) {
            int c0 = bcol + wc * 64 + nb8 * 8 + qcol;
            float* d = acc[mi][nb8];
            if (Cf) {
                *(float2*)(Cf + (size_t)r0 * N + c0)       = make_float2(d[0], d[1]);
                *(float2*)(Cf + (size_t)(r0 + 8) * N + c0) = make_float2(d[2], d[3]);
            } else {
                const float sc = (c0 < qcols) ? qscale : 1.f;
                float h0,l0,h1,l1;
                split_h(d[0] * sc, h0, l0); split_h(d[1] * sc, h1, l1);
                *(uint32_t*)(Ch + (size_t)r0 * N + c0) = pack_h2(h0, h1);
                *(uint32_t*)(Cl + (size_t)r0 * N + c0) = pack_h2(l0, l1);
                split_h(d[2] * sc, h0, l0); split_h(d[3] * sc, h1, l1);
                *(uint32_t*)(Ch + (size_t)(r0 + 8) * N + c0) = pack_h2(h0, h1);
                *(uint32_t*)(Cl + (size_t)(r0 + 8) * N + c0) = pack_h2(l0, l1);
            }
        }
    }
}

// ===========================================================================
// HMMA flash attention, fp16x2: S = (Qh+Ql)Kh^T, O = (Ph+Pl)Vh.
// Grid: (SEQ/256, NH, BATCH). 512 threads = 16 warps; warp w owns q rows
// [w*16, w*16+16). Q hi/lo persists in smem; Kh/Vh 3-stage cp.async ring.
// ===========================================================================
#define SK 72                          // fp16 elems per row (144 B stride)
#define AQHI 0
#define AQLO (256 * SK * 2)            // 36864
#define AKV  (2 * 256 * SK * 2)        // 73728
#define KVST (2 * 64 * SK * 2)         // 18432 per stage (Kh + Vh)
#define OKH  0
#define OVH  (64 * SK * 2)             // 9216
#define ATTN_SMEM_BYTES (AKV + 3 * KVST)   // 129024

__global__ __launch_bounds__(512, 1)
void attn_hmma()
{
    extern __shared__ char dsm[];
    const uint32_t su = smem_to_u32(dsm);

    const int tid = threadIdx.x;
    const int wid = tid >> 5;
    const int lid = tid & 31;
    const int b  = blockIdx.z;
    const int h  = blockIdx.y;
    const int q0 = blockIdx.x * 256;

    const uint32_t uQhi = su + AQHI, uQlo = su + AQLO;

    // KV copy (512 thr): arr = tid>>8 (0:Kh 1:Vh), t = tid&255,
    // row = t>>2, quarter = t&3 (32 B each)
    const int cv_arr = tid >> 8;
    const int cv_r   = (tid >> 2) & 63;
    const int cv_q   = tid & 3;
    const int cv_col = DM + cv_arr * DM + h * HD + cv_q * 16;

    auto issue_kv = [&](int kb) {
        const uint32_t sb = su + AKV + (uint32_t)(kb % 3) * KVST
                            + cv_arr * (64 * SK * 2) + cv_r * (SK * 2) + cv_q * 32;
        const __half* gp = g_qkvh + (size_t)(b * SEQ + kb * 64 + cv_r) * QKVN + cv_col;
        CP_ASYNC16(sb,      gp);
        CP_ASYNC16(sb + 16, gp + 8);
    };

    // ---- issue Q (hi/lo) + KV block 0 as group 0
    {
        const int qr = tid >> 1;
        const __half* gq =
            ((tid & 1) ? g_qkvl : g_qkvh) + (size_t)(b * SEQ + q0 + qr) * QKVN + h * HD;
        uint32_t sq = ((tid & 1) ? uQlo : uQhi) + qr * (SK * 2);
#pragma unroll
        for (int c = 0; c < 8; c++)
            CP_ASYNC16(sq + c * 16, gq + c * 8);
    }
    issue_kv(0); CP_COMMIT();
    issue_kv(1); CP_COMMIT();

    float o[8][4];
#pragma unroll
    for (int j = 0; j < 8; j++)
#pragma unroll
        for (int q = 0; q < 4; q++) o[j][q] = 0.f;
    float m0 = -1e30f, m1 = -1e30f, l0 = 0.f, l1 = 0.f;

    for (int kb = 0; kb < SEQ / 64; kb++) {
        if (kb + 1 < SEQ / 64) { CP_WAIT1(); } else { CP_WAIT0(); }
        __syncthreads();
        if (kb + 2 < SEQ / 64) { issue_kv(kb + 2); CP_COMMIT(); }

        const uint32_t stB = su + AKV + (uint32_t)(kb % 3) * KVST;
        const uint32_t uKh = stB + OKH, uVh = stB + OVH;

        // ---- S = (Qh+Ql) Kh^T  (16 x 64 per warp), 2 MMAs/product
        float s[8][4];
#pragma unroll
        for (int j = 0; j < 8; j++)
#pragma unroll
            for (int q = 0; q < 4; q++) s[j][q] = 0.f;

#pragma unroll
        for (int t = 0; t < 4; t++) {
            uint32_t qh[4], ql[4];
            {
                uint32_t row = wid * 16 + (lid & 15);
                uint32_t off = (row * SK + t * 16 + (lid >> 4) * 8) * 2;
                ldsm_x4(qh, uQhi + off);
                ldsm_x4(ql, uQlo + off);
            }
#pragma unroll
            for (int jp = 0; jp < 2; jp++) {
                uint32_t kh[2][4];
#pragma unroll
                for (int i = 0; i < 2; i++) {
                    const int j2 = jp * 2 + i;
                    uint32_t off = ((j2 * 16 + (lid & 7) + ((lid >> 4) & 1) * 8) * SK
                                    + t * 16 + ((lid >> 3) & 1) * 8) * 2;
                    ldsm_x4(kh[i], uKh + off);
                }
#pragma unroll
                for (int pass = 0; pass < 2; pass++) {
#pragma unroll
                    for (int i = 0; i < 2; i++) {
                        const int j2 = jp * 2 + i;
                        const uint32_t* af = pass ? ql : qh;
                        mma16816(s[j2 * 2],     af, &kh[i][0]);
                        mma16816(s[j2 * 2 + 1], af, &kh[i][2]);
                    }
                }
            }
        }

        // ---- online softmax (log2 domain) + pack P hi/lo
        uint32_t phi[4][4], plo[4][4];
        {
            float mx0 = s[0][0], mx1 = s[0][2];
#pragma unroll
            for (int j = 0; j < 8; j++) {
                mx0 = fmaxf(mx0, fmaxf(s[j][0], s[j][1]));
                mx1 = fmaxf(mx1, fmaxf(s[j][2], s[j][3]));
            }
            mx0 = fmaxf(mx0, __shfl_xor_sync(0xffffffff, mx0, 1));
            mx0 = fmaxf(mx0, __shfl_xor_sync(0xffffffff, mx0, 2));
            mx1 = fmaxf(mx1, __shfl_xor_sync(0xffffffff, mx1, 1));
            mx1 = fmaxf(mx1, __shfl_xor_sync(0xffffffff, mx1, 2));

            const float mn0 = fmaxf(m0, mx0);
            const float mn1 = fmaxf(m1, mx1);
            const float c0 = ex2f(m0 - mn0);
            const float c1 = ex2f(m1 - mn1);
            m0 = mn0; m1 = mn1;

            float rl0 = 0.f, rl1 = 0.f;
#pragma unroll
            for (int j = 0; j < 8; j++) {
                s[j][0] = ex2f(s[j][0] - mn0); rl0 += s[j][0];
                s[j][1] = ex2f(s[j][1] - mn0); rl0 += s[j][1];
                s[j][2] = ex2f(s[j][2] - mn1); rl1 += s[j][2];
                s[j][3] = ex2f(s[j][3] - mn1); rl1 += s[j][3];
            }
            rl0 += __shfl_xor_sync(0xffffffff, rl0, 1);
            rl0 += __shfl_xor_sync(0xffffffff, rl0, 2);
            rl1 += __shfl_xor_sync(0xffffffff, rl1, 1);
            rl1 += __shfl_xor_sync(0xffffffff, rl1, 2);
            l0 = l0 * c0 + rl0;
            l1 = l1 * c1 + rl1;

#pragma unroll
            for (int j = 0; j < 8; j++) {
                o[j][0] *= c0; o[j][1] *= c0;
                o[j][2] *= c1; o[j][3] *= c1;
            }

#pragma unroll
            for (int t = 0; t < 4; t++) {
                const int j = 2 * t;
                float h0,lo0,h1,lo1;
                split_h(s[j][0], h0, lo0);   split_h(s[j][1], h1, lo1);
                phi[t][0] = pack_h2(h0, h1);  plo[t][0] = pack_h2(lo0, lo1);
                split_h(s[j][2], h0, lo0);   split_h(s[j][3], h1, lo1);
                phi[t][1] = pack_h2(h0, h1);  plo[t][1] = pack_h2(lo0, lo1);
                split_h(s[j+1][0], h0, lo0); split_h(s[j+1][1], h1, lo1);
                phi[t][2] = pack_h2(h0, h1);  plo[t][2] = pack_h2(lo0, lo1);
                split_h(s[j+1][2], h0, lo0); split_h(s[j+1][3], h1, lo1);
                phi[t][3] = pack_h2(h0, h1);  plo[t][3] = pack_h2(lo0, lo1);
            }
        }

        // ---- O += (Ph+Pl) Vh  (2 MMAs/product)
#pragma unroll
        for (int t = 0; t < 4; t++) {
#pragma unroll
            for (int jp = 0; jp < 2; jp++) {
                uint32_t vh[2][4];
#pragma unroll
                for (int i = 0; i < 2; i++) {
                    const int j2 = jp * 2 + i;
                    uint32_t off = ((t * 16 + (lid & 15)) * SK
                                    + j2 * 16 + (lid >> 4) * 8) * 2;
                    ldsm_x4_t(vh[i], uVh + off);
                }
#pragma unroll
                for (int pass = 0; pass < 2; pass++) {
#pragma unroll
                    for (int i = 0; i < 2; i++) {
                        const int j2 = jp * 2 + i;
                        const uint32_t* af = pass ? plo[t] : phi[t];
                        mma16816(o[j2 * 2],     af, &vh[i][0]);
                        mma16816(o[j2 * 2 + 1], af, &vh[i][2]);
                    }
                }
            }
        }
    }

    // ---- epilogue: write hi/lo fp16 attention output
    {
        const float inv0 = 1.f / l0;
        const float inv1 = 1.f / l1;
        const int gr0 = q0 + wid * 16 + (lid >> 2);
        const int col = h * HD + (lid & 3) * 2;
#pragma unroll
        for (int j = 0; j < 8; j++) {
            size_t i0 = (size_t)(b * SEQ + gr0) * DM + col + j * 8;
            size_t i1 = (size_t)(b * SEQ + gr0 + 8) * DM + col + j * 8;
            float h0,lo0,h1,lo1;
            split_h(o[j][0] * inv0, h0, lo0);
            split_h(o[j][1] * inv0, h1, lo1);
            *(uint32_t*)(g_atth + i0) = pack_h2(h0, h1);
            *(uint32_t*)(g_attl + i0) = pack_h2(lo0, lo1);
            split_h(o[j][2] * inv1, h0, lo0);
            split_h(o[j][3] * inv1, h1, lo1);
            *(uint32_t*)(g_atth + i1) = pack_h2(h0, h1);
            *(uint32_t*)(g_attl + i1) = pack_h2(lo0, lo1);
        }
    }
}

// ---------------------------------------------------------------------------
extern "C" void kernel_launch(void* const* d_in, const int* in_sizes, int n_in,
                              void* d_out, int out_size)
{
    const float* x     = (const float*)d_in[0];   // [4,2048,1024]
    const float* w_qkv = (const float*)d_in[1];   // [1024,3072]
    const float* w_out = (const float*)d_in[2];   // [1024,1024]
    float* out = (float*)d_out;                   // [4,2048,1024]

    __half *xh, *xl, *wqh, *wql, *woh, *wol, *qkvh, *qkvl, *atth, *attl;
    cudaGetSymbolAddress((void**)&xh,  g_xh);   cudaGetSymbolAddress((void**)&xl,  g_xl);
    cudaGetSymbolAddress((void**)&wqh, g_wqh);  cudaGetSymbolAddress((void**)&wql, g_wql);
    cudaGetSymbolAddress((void**)&woh, g_woh);  cudaGetSymbolAddress((void**)&wol, g_wol);
    cudaGetSymbolAddress((void**)&qkvh, g_qkvh); cudaGetSymbolAddress((void**)&qkvl, g_qkvl);
    cudaGetSymbolAddress((void**)&atth, g_atth); cudaGetSymbolAddress((void**)&attl, g_attl);

    cudaFuncSetAttribute(gemm_async,
                         cudaFuncAttributeMaxDynamicSharedMemorySize,
                         GEMM_SMEM_BYTES);
    cudaFuncSetAttribute(attn_hmma,
                         cudaFuncAttributeMaxDynamicSharedMemorySize,
                         ATTN_SMEM_BYTES);

    const float QSCALE = 0.125f * 1.4426950408889634f;   // (1/sqrt(64))*log2(e)

    // 0) split inputs to fp16 hi/lo
    {
        int n4x = MROWS * DM / 4;
        split_kernel<<<(n4x + 255) / 256, 256>>>(x, xh, xl, n4x);
        int n4q = DM * QKVN / 4;
        split_kernel<<<(n4q + 255) / 256, 256>>>(w_qkv, wqh, wql, n4q);
        int n4o = DM * DM / 4;
        split_kernel<<<(n4o + 255) / 256, 256>>>(w_out, woh, wol, n4o);
    }

    // 1) QKV projection -> hi/lo fp16 (Q columns pre-scaled by QSCALE)
    {
        dim3 grid(QKVN / 256, MROWS / 128);
        gemm_async<<<grid, 512, GEMM_SMEM_BYTES>>>(
            xh, xl, wqh, nullptr, qkvh, qkvl,
            MROWS, QKVN, DM, QSCALE, DM);
    }

    // 2) Attention (HMMA flash, cp.async K/V)
    {
        dim3 grid(SEQ / 256, NH, BATCH);
        attn_hmma<<<grid, 512, ATTN_SMEM_BYTES>>>();
    }

    // 3) Output projection -> fp32 d_out
    {
        dim3 grid(DM / 256, MROWS / 128);
        gemm_async<<<grid, 512, GEMM_SMEM_BYTES>>>(
            atth, attl, woh, out, nullptr, nullptr,
            MROWS, DM, DM, 1.f, 0);
    }
}

// round 11
// speedup vs baseline: 2.2867x; 1.5996x over previous
#include <cuda_runtime.h>
#include <cuda_fp16.h>
#include <math.h>
#include <cstdint>

#define BATCH 4
#define SEQ   2048
#define DM    1024
#define NH    16
#define HD    64
#define QKVN  (3*DM)
#define MROWS (BATCH*SEQ)   // 8192

// ---------------------------------------------------------------------------
// Persistent fp16 arrays (no dynamic allocation allowed)
// ---------------------------------------------------------------------------
__device__ __half g_xh[(size_t)MROWS * DM];
__device__ __half g_wqh[(size_t)DM * QKVN];
__device__ __half g_woh[(size_t)DM * DM];
__device__ __half g_qkvh[(size_t)MROWS * QKVN];
__device__ __half g_atth[(size_t)MROWS * DM];

// ===========================================================================
// Helpers
// ===========================================================================
__device__ __forceinline__ void ldsm_x4(uint32_t* r, uint32_t addr) {
    asm volatile("ldmatrix.sync.aligned.m8n8.x4.shared.b16 {%0,%1,%2,%3}, [%4];"
        : "=r"(r[0]), "=r"(r[1]), "=r"(r[2]), "=r"(r[3]) : "r"(addr));
}
__device__ __forceinline__ void ldsm_x4_t(uint32_t* r, uint32_t addr) {
    asm volatile("ldmatrix.sync.aligned.m8n8.x4.trans.shared.b16 {%0,%1,%2,%3}, [%4];"
        : "=r"(r[0]), "=r"(r[1]), "=r"(r[2]), "=r"(r[3]) : "r"(addr));
}
__device__ __forceinline__ void mma16816(float* d, const uint32_t* a, const uint32_t* b) {
    asm volatile(
        "mma.sync.aligned.m16n8k16.row.col.f32.f16.f16.f32 "
        "{%0,%1,%2,%3}, {%4,%5,%6,%7}, {%8,%9}, {%0,%1,%2,%3};"
        : "+f"(d[0]), "+f"(d[1]), "+f"(d[2]), "+f"(d[3])
        : "r"(a[0]), "r"(a[1]), "r"(a[2]), "r"(a[3]), "r"(b[0]), "r"(b[1]));
}
__device__ __forceinline__ uint32_t smem_to_u32(const void* smem_ptr) {
    uint32_t addr;
    asm("{ .reg .u64 tmp; cvta.to.shared.u64 tmp, %1; cvt.u32.u64 %0, tmp; }"
        : "=r"(addr) : "l"(smem_ptr));
    return addr;
}
__device__ __forceinline__ float ex2f(float x) {
    float y;
    asm("ex2.approx.f32 %0, %1;" : "=f"(y) : "f"(x));
    return y;
}
__device__ __forceinline__ uint32_t pack_h2(float x0, float x1) {
    __half2 t = __floats2half2_rn(x0, x1);
    return *(uint32_t*)&t;
}

#define CP_ASYNC16(saddr, gptr) \
    asm volatile("cp.async.cg.shared.global [%0], [%1], 16;" \
                 :: "r"(saddr), "l"(gptr))
#define CP_COMMIT()  asm volatile("cp.async.commit_group;")
#define CP_WAIT0()   asm volatile("cp.async.wait_group 0;")
#define CP_WAIT1()   asm volatile("cp.async.wait_group 1;")

// ===========================================================================
// Convert kernel: fp32 -> fp16
// ===========================================================================
__global__ void cvt_kernel(const float* __restrict__ s,
                           __half* __restrict__ h, int n4)
{
    int i = blockIdx.x * blockDim.x + threadIdx.x;
    if (i >= n4) return;
    float4 v = ((const float4*)s)[i];
    ((uint2*)h)[i] = make_uint2(pack_h2(v.x, v.y), pack_h2(v.z, v.w));
}

// ===========================================================================
// cp.async fp16 GEMM: C = A @ B, fp16 operands, fp32 accumulate.
// CTA tile 128x256, BK=32, 512 threads (16 warps, 32x64 warp tiles, 4x4).
// 3-stage cp.async ring.
// ===========================================================================
#define GOA 0
#define GOB 10240                        // A: 128 rows x 80 B
#define GSTAGE_B 27136                   // + B: 32 rows x 528 B
#define GEMM_SMEM_BYTES (3 * GSTAGE_B)   // 81408

__global__ __launch_bounds__(512, 1)
void gemm_async(const __half* __restrict__ A, const __half* __restrict__ B,
                float* __restrict__ Cf, __half* __restrict__ Ch,
                int M, int N, int K, float qscale, int qcols)
{
    extern __shared__ char smem[];
    const uint32_t su = smem_to_u32(smem);

    const int tid = threadIdx.x;
    const int wid = tid >> 5;
    const int lid = tid & 31;
    const int brow = blockIdx.y * 128;
    const int bcol = blockIdx.x * 256;

    const int wr = wid >> 2;     // 0..3 -> m offset wr*32
    const int wc = wid & 3;      // 0..3 -> n offset wc*64

    const int nkt = K >> 5;

    // copy-thread assignments (512 threads)
    const int ar  = tid >> 2;            // A row 0..127
    const int ac  = tid & 3;             // A 16B chunk 0..3
    const int br  = tid >> 4;            // B row 0..31
    const int bc  = (tid & 15) * 2;      // B chunk base (2 chunks of 16B)

    auto issue_tile = [&](int kt) {
        const uint32_t sb = su + (uint32_t)(kt % 3) * GSTAGE_B;
        const int k0 = kt << 5;
        const __half* ga = A + (size_t)(brow + ar) * K + k0 + ac * 8;
        CP_ASYNC16(sb + GOA + ar * 80 + ac * 16, ga);
        const __half* gb = B + (size_t)(k0 + br) * N + bcol + bc * 8;
        uint32_t sbb = sb + GOB + br * 528 + bc * 16;
        CP_ASYNC16(sbb,      gb);
        CP_ASYNC16(sbb + 16, gb + 8);
    };

    float acc[2][8][4];
#pragma unroll
    for (int i = 0; i < 2; i++)
#pragma unroll
        for (int j = 0; j < 8; j++)
#pragma unroll
            for (int q = 0; q < 4; q++) acc[i][j][q] = 0.f;

    issue_tile(0); CP_COMMIT();
    issue_tile(1); CP_COMMIT();

    for (int kt = 0; kt < nkt; kt++) {
        if (kt + 1 < nkt) { CP_WAIT1(); } else { CP_WAIT0(); }
        __syncthreads();
        if (kt + 2 < nkt) { issue_tile(kt + 2); CP_COMMIT(); }

        const uint32_t sb = su + (uint32_t)(kt % 3) * GSTAGE_B;
#pragma unroll
        for (int ks = 0; ks < 2; ks++) {
            uint32_t ah[2][4];
#pragma unroll
            for (int mi = 0; mi < 2; mi++) {
                uint32_t row = wr * 32 + mi * 16 + (lid & 15);
                uint32_t col = ks * 16 + (lid >> 4) * 8;
                ldsm_x4(ah[mi], sb + GOA + row * 80 + col * 2);
            }
#pragma unroll
            for (int nbp = 0; nbp < 2; nbp++) {
                uint32_t bh[2][4];
#pragma unroll
                for (int i = 0; i < 2; i++) {
                    const int nb = nbp * 2 + i;
                    uint32_t row = ks * 16 + (lid & 15);
                    uint32_t col = wc * 64 + nb * 16 + (lid >> 4) * 8;
                    ldsm_x4_t(bh[i], sb + GOB + row * 528 + col * 2);
                }
#pragma unroll
                for (int i = 0; i < 2; i++) {
                    const int nb = nbp * 2 + i;
#pragma unroll
                    for (int mi = 0; mi < 2; mi++) {
                        mma16816(acc[mi][nb * 2],     ah[mi], &bh[i][0]);
                        mma16816(acc[mi][nb * 2 + 1], ah[mi], &bh[i][2]);
                    }
                }
            }
        }
    }

    // ---- epilogue ----
    const int qrow = lid >> 2;
    const int qcol = (lid & 3) * 2;
#pragma unroll
    for (int mi = 0; mi < 2; mi++) {
        int r0 = brow + wr * 32 + mi * 16 + qrow;
#pragma unroll
        for (int nb8 = 0; nb8 < 8; nb8++) {
            int c0 = bcol + wc * 64 + nb8 * 8 + qcol;
            float* d = acc[mi][nb8];
            if (Cf) {
                *(float2*)(Cf + (size_t)r0 * N + c0)       = make_float2(d[0], d[1]);
                *(float2*)(Cf + (size_t)(r0 + 8) * N + c0) = make_float2(d[2], d[3]);
            } else {
                const float sc = (c0 < qcols) ? qscale : 1.f;
                *(uint32_t*)(Ch + (size_t)r0 * N + c0)       = pack_h2(d[0] * sc, d[1] * sc);
                *(uint32_t*)(Ch + (size_t)(r0 + 8) * N + c0) = pack_h2(d[2] * sc, d[3] * sc);
            }
        }
    }
}

// ===========================================================================
// HMMA flash attention, pure fp16 operands, fp32 accumulate.
// Grid: (SEQ/256, NH, BATCH). 512 threads = 16 warps; warp w owns q rows
// [w*16, w*16+16). Q persists in smem; Kh/Vh 3-stage cp.async ring.
// ===========================================================================
#define SK 72                          // fp16 elems per row (144 B stride)
#define AQ  0
#define AKV (256 * SK * 2)             // 36864
#define KVST (2 * 64 * SK * 2)         // 18432 per stage (K + V)
#define OKH  0
#define OVH  (64 * SK * 2)             // 9216
#define ATTN_SMEM_BYTES (AKV + 3 * KVST)   // 92160

__global__ __launch_bounds__(512, 1)
void attn_hmma()
{
    extern __shared__ char dsm[];
    const uint32_t su = smem_to_u32(dsm);

    const int tid = threadIdx.x;
    const int wid = tid >> 5;
    const int lid = tid & 31;
    const int b  = blockIdx.z;
    const int h  = blockIdx.y;
    const int q0 = blockIdx.x * 256;

    const uint32_t uQ = su + AQ;

    // KV copy (512 thr): arr = tid>>8 (0:K 1:V), row = (tid>>2)&63, quarter = tid&3
    const int cv_arr = tid >> 8;
    const int cv_r   = (tid >> 2) & 63;
    const int cv_q   = tid & 3;
    const int cv_col = DM + cv_arr * DM + h * HD + cv_q * 16;

    auto issue_kv = [&](int kb) {
        const uint32_t sb = su + AKV + (uint32_t)(kb % 3) * KVST
                            + cv_arr * (64 * SK * 2) + cv_r * (SK * 2) + cv_q * 32;
        const __half* gp = g_qkvh + (size_t)(b * SEQ + kb * 64 + cv_r) * QKVN + cv_col;
        CP_ASYNC16(sb,      gp);
        CP_ASYNC16(sb + 16, gp + 8);
    };

    // ---- issue Q + KV block 0 as group 0
    {
        const int qr = tid >> 1;
        const int qc = (tid & 1) * 32;
        const __half* gq = g_qkvh + (size_t)(b * SEQ + q0 + qr) * QKVN + h * HD + qc;
        uint32_t sq = uQ + qr * (SK * 2) + qc * 2;
#pragma unroll
        for (int c = 0; c < 4; c++)
            CP_ASYNC16(sq + c * 16, gq + c * 8);
    }
    issue_kv(0); CP_COMMIT();
    issue_kv(1); CP_COMMIT();

    float o[8][4];
#pragma unroll
    for (int j = 0; j < 8; j++)
#pragma unroll
        for (int q = 0; q < 4; q++) o[j][q] = 0.f;
    float m0 = -1e30f, m1 = -1e30f, l0 = 0.f, l1 = 0.f;

    for (int kb = 0; kb < SEQ / 64; kb++) {
        if (kb + 1 < SEQ / 64) { CP_WAIT1(); } else { CP_WAIT0(); }
        __syncthreads();
        if (kb + 2 < SEQ / 64) { issue_kv(kb + 2); CP_COMMIT(); }

        const uint32_t stB = su + AKV + (uint32_t)(kb % 3) * KVST;
        const uint32_t uKh = stB + OKH, uVh = stB + OVH;

        // ---- S = Q Kh^T  (16 x 64 per warp)
        float s[8][4];
#pragma unroll
        for (int j = 0; j < 8; j++)
#pragma unroll
            for (int q = 0; q < 4; q++) s[j][q] = 0.f;

#pragma unroll
        for (int t = 0; t < 4; t++) {
            uint32_t qh[4];
            {
                uint32_t row = wid * 16 + (lid & 15);
                uint32_t off = (row * SK + t * 16 + (lid >> 4) * 8) * 2;
                ldsm_x4(qh, uQ + off);
            }
#pragma unroll
            for (int jp = 0; jp < 2; jp++) {
                uint32_t kh[2][4];
#pragma unroll
                for (int i = 0; i < 2; i++) {
                    const int j2 = jp * 2 + i;
                    uint32_t off = ((j2 * 16 + (lid & 7) + ((lid >> 4) & 1) * 8) * SK
                                    + t * 16 + ((lid >> 3) & 1) * 8) * 2;
                    ldsm_x4(kh[i], uKh + off);
                }
#pragma unroll
                for (int i = 0; i < 2; i++) {
                    const int j2 = jp * 2 + i;
                    mma16816(s[j2 * 2],     qh, &kh[i][0]);
                    mma16816(s[j2 * 2 + 1], qh, &kh[i][2]);
                }
            }
        }

        // ---- online softmax (log2 domain) + pack P fp16
        uint32_t ph[4][4];
        {
            float mx0 = s[0][0], mx1 = s[0][2];
#pragma unroll
            for (int j = 0; j < 8; j++) {
                mx0 = fmaxf(mx0, fmaxf(s[j][0], s[j][1]));
                mx1 = fmaxf(mx1, fmaxf(s[j][2], s[j][3]));
            }
            mx0 = fmaxf(mx0, __shfl_xor_sync(0xffffffff, mx0, 1));
            mx0 = fmaxf(mx0, __shfl_xor_sync(0xffffffff, mx0, 2));
            mx1 = fmaxf(mx1, __shfl_xor_sync(0xffffffff, mx1, 1));
            mx1 = fmaxf(mx1, __shfl_xor_sync(0xffffffff, mx1, 2));

            const float mn0 = fmaxf(m0, mx0);
            const float mn1 = fmaxf(m1, mx1);
            const float c0 = ex2f(m0 - mn0);
            const float c1 = ex2f(m1 - mn1);
            m0 = mn0; m1 = mn1;

            float rl0 = 0.f, rl1 = 0.f;
#pragma unroll
            for (int j = 0; j < 8; j++) {
                s[j][0] = ex2f(s[j][0] - mn0); rl0 += s[j][0];
                s[j][1] = ex2f(s[j][1] - mn0); rl0 += s[j][1];
                s[j][2] = ex2f(s[j][2] - mn1); rl1 += s[j][2];
                s[j][3] = ex2f(s[j][3] - mn1); rl1 += s[j][3];
            }
            rl0 += __shfl_xor_sync(0xffffffff, rl0, 1);
            rl0 += __shfl_xor_sync(0xffffffff, rl0, 2);
            rl1 += __shfl_xor_sync(0xffffffff, rl1, 1);
            rl1 += __shfl_xor_sync(0xffffffff, rl1, 2);
            l0 = l0 * c0 + rl0;
            l1 = l1 * c1 + rl1;

#pragma unroll
            for (int j = 0; j < 8; j++) {
                o[j][0] *= c0; o[j][1] *= c0;
                o[j][2] *= c1; o[j][3] *= c1;
            }

#pragma unroll
            for (int t = 0; t < 4; t++) {
                const int j = 2 * t;
                ph[t][0] = pack_h2(s[j][0],   s[j][1]);
                ph[t][1] = pack_h2(s[j][2],   s[j][3]);
                ph[t][2] = pack_h2(s[j+1][0], s[j+1][1]);
                ph[t][3] = pack_h2(s[j+1][2], s[j+1][3]);
            }
        }

        // ---- O += P Vh
#pragma unroll
        for (int t = 0; t < 4; t++) {
#pragma unroll
            for (int jp = 0; jp < 2; jp++) {
                uint32_t vh[2][4];
#pragma unroll
                for (int i = 0; i < 2; i++) {
                    const int j2 = jp * 2 + i;
                    uint32_t off = ((t * 16 + (lid & 15)) * SK
                                    + j2 * 16 + (lid >> 4) * 8) * 2;
                    ldsm_x4_t(vh[i], uVh + off);
                }
#pragma unroll
                for (int i = 0; i < 2; i++) {
                    const int j2 = jp * 2 + i;
                    mma16816(o[j2 * 2],     ph[t], &vh[i][0]);
                    mma16816(o[j2 * 2 + 1], ph[t], &vh[i][2]);
                }
            }
        }
    }

    // ---- epilogue: write fp16 attention output
    {
        const float inv0 = 1.f / l0;
        const float inv1 = 1.f / l1;
        const int gr0 = q0 + wid * 16 + (lid >> 2);
        const int col = h * HD + (lid & 3) * 2;
#pragma unroll
        for (int j = 0; j < 8; j++) {
            size_t i0 = (size_t)(b * SEQ + gr0) * DM + col + j * 8;
            size_t i1 = (size_t)(b * SEQ + gr0 + 8) * DM + col + j * 8;
            *(uint32_t*)(g_atth + i0) = pack_h2(o[j][0] * inv0, o[j][1] * inv0);
            *(uint32_t*)(g_atth + i1) = pack_h2(o[j][2] * inv1, o[j][3] * inv1);
        }
    }
}

// ---------------------------------------------------------------------------
extern "C" void kernel_launch(void* const* d_in, const int* in_sizes, int n_in,
                              void* d_out, int out_size)
{
    const float* x     = (const float*)d_in[0];   // [4,2048,1024]
    const float* w_qkv = (const float*)d_in[1];   // [1024,3072]
    const float* w_out = (const float*)d_in[2];   // [1024,1024]
    float* out = (float*)d_out;                   // [4,2048,1024]

    __half *xh, *wqh, *woh, *qkvh, *atth;
    cudaGetSymbolAddress((void**)&xh,   g_xh);
    cudaGetSymbolAddress((void**)&wqh,  g_wqh);
    cudaGetSymbolAddress((void**)&woh,  g_woh);
    cudaGetSymbolAddress((void**)&qkvh, g_qkvh);
    cudaGetSymbolAddress((void**)&atth, g_atth);

    cudaFuncSetAttribute(gemm_async,
                         cudaFuncAttributeMaxDynamicSharedMemorySize,
                         GEMM_SMEM_BYTES);
    cudaFuncSetAttribute(attn_hmma,
                         cudaFuncAttributeMaxDynamicSharedMemorySize,
                         ATTN_SMEM_BYTES);

    const float QSCALE = 0.125f * 1.4426950408889634f;   // (1/sqrt(64))*log2(e)

    // 0) convert inputs to fp16
    {
        int n4x = MROWS * DM / 4;
        cvt_kernel<<<(n4x + 255) / 256, 256>>>(x, xh, n4x);
        int n4q = DM * QKVN / 4;
        cvt_kernel<<<(n4q + 255) / 256, 256>>>(w_qkv, wqh, n4q);
        int n4o = DM * DM / 4;
        cvt_kernel<<<(n4o + 255) / 256, 256>>>(w_out, woh, n4o);
    }

    // 1) QKV projection -> fp16 (Q columns pre-scaled by QSCALE)
    {
        dim3 grid(QKVN / 256, MROWS / 128);
        gemm_async<<<grid, 512, GEMM_SMEM_BYTES>>>(
            xh, wqh, nullptr, qkvh, MROWS, QKVN, DM, QSCALE, DM);
    }

    // 2) Attention (HMMA flash, cp.async K/V)
    {
        dim3 grid(SEQ / 256, NH, BATCH);
        attn_hmma<<<grid, 512, ATTN_SMEM_BYTES>>>();
    }

    // 3) Output projection -> fp32 d_out
    {
        dim3 grid(DM / 256, MROWS / 128);
        gemm_async<<<grid, 512, GEMM_SMEM_BYTES>>>(
            atth, woh, out, nullptr, MROWS, DM, DM, 1.f, 0);
    }
}